// round 3
// baseline (speedup 1.0000x reference)
#include <cuda_runtime.h>
#include <cstdint>

// LinearInterpolator on GB300 — branchless upward-scan version.
//  - build_lut_kernel: base[j] = largest knot index i with cell(x_i) <= j-1
//    (clamped to [0, n-2]). cell() is the SAME monotone fmaf in both kernels,
//    so for any sample x with cell(x)=j the true interval index is >= base[j]:
//    the main kernel only ever scans UPWARD.
//  - interp_kernel: SMEM = s_x[n+8] f32 (padded with +INF), s_ys[n] (y_i, slope_i)
//    float2, u16 base LUT. Per sample: cell -> base -> 4 eager branchless
//    compare-and-bump steps -> (warp-uniform-guarded rare loop) -> one FMA.

#define LUT_SIZE 16384
#define THREADS  1024

__device__ unsigned short g_lut[LUT_SIZE + 2];

__device__ __forceinline__ int cell_of(float v, float inv_w, float c0) {
    // (int)fmaf(v, inv_w, c0): monotone nondecreasing in v for inv_w > 0,
    // identical instruction sequence in build + main kernels.
    return (int)fmaf(v, inv_w, c0);
}

__global__ void build_lut_kernel(const float* __restrict__ xp, int n) {
    int j = blockIdx.x * blockDim.x + threadIdx.x;
    if (j > LUT_SIZE) return;
    float x_lo = __ldg(&xp[0]);
    float x_hi = __ldg(&xp[n - 1]);
    float inv_w = __fdiv_rn((float)LUT_SIZE, __fsub_rn(x_hi, x_lo));
    float c0 = __fmul_rn(-x_lo, inv_w);
    // count = #{i : cell(x_i) <= j-1}; base = max(count-1, 0)
    int lo = 0, hi = n;
    #pragma unroll 1
    while (lo < hi) {
        int mid = (lo + hi) >> 1;
        if (cell_of(__ldg(&xp[mid]), inv_w, c0) <= j - 1) lo = mid + 1;
        else hi = mid;
    }
    int base = lo - 1;
    if (base < 0) base = 0;
    if (base > n - 2) base = n - 2;
    g_lut[j] = (unsigned short)base;
}

extern __shared__ unsigned char smem_raw[];

__device__ __forceinline__ float interp1(float x,
                                         const float* __restrict__ s_x,
                                         const float2* __restrict__ s_ys,
                                         const unsigned short* __restrict__ s_lut,
                                         float inv_w, float c0) {
    int j = cell_of(x, inv_w, c0);
    int idx = (int)s_lut[j];
    // Four eager branchless up-steps. s_x padded with +INF so idx+1..idx+8
    // reads are always in-bounds and compares fail past the last knot.
    int p;
    p = (s_x[idx + 1] <= x);             idx += p;
    p = p & (int)(s_x[idx + 1] <= x);    idx += p;
    p = p & (int)(s_x[idx + 1] <= x);    idx += p;
    p = p & (int)(s_x[idx + 1] <= x);    idx += p;
    // Rare tail (needs >= 5 steps): warp-uniform guard, no per-lane divergence
    // in the common case.
    if (__any_sync(0xFFFFFFFFu, p)) {
        #pragma unroll 1
        while (p) { p = (s_x[idx + 1] <= x); idx += p; }
    }
    float xi = s_x[idx];
    float2 ysv = s_ys[idx];              // (y_i, slope_i)
    return fmaf(ysv.y, __fsub_rn(x, xi), ysv.x);
}

__global__ __launch_bounds__(THREADS, 1)
void interp_kernel(const float* __restrict__ xs, const float* __restrict__ xp,
                   const float* __restrict__ yp, float* __restrict__ out,
                   int total, int n) {
    float* s_x = reinterpret_cast<float*>(smem_raw);                     // n+8 f32
    float2* s_ys = reinterpret_cast<float2*>(smem_raw + (size_t)(n + 8) * 4);
    unsigned short* s_lut =
        reinterpret_cast<unsigned short*>(smem_raw + (size_t)(n + 8) * 4
                                                   + (size_t)n * 8);

    for (int i = threadIdx.x; i < n; i += blockDim.x) {
        float xi = xp[i];
        float yi = yp[i];
        s_x[i] = xi;
        float sl = 0.0f;
        if (i < n - 1) sl = __fdiv_rn(yp[i + 1] - yi, xp[i + 1] - xi);
        s_ys[i] = make_float2(yi, sl);
    }
    if (threadIdx.x < 8)                 // +INF padding for eager steps
        s_x[n + threadIdx.x] = __int_as_float(0x7F800000);
    for (int i = threadIdx.x; i <= LUT_SIZE; i += blockDim.x)
        s_lut[i] = g_lut[i];
    __syncthreads();

    float x_lo = s_x[0];
    float x_hi = s_x[n - 1];
    float inv_w = __fdiv_rn((float)LUT_SIZE, __fsub_rn(x_hi, x_lo));
    float c0 = __fmul_rn(-x_lo, inv_w);

    int tid = blockIdx.x * blockDim.x + threadIdx.x;
    int stride = gridDim.x * blockDim.x;
    int T4 = total >> 2;

    const float4* __restrict__ xs4 = reinterpret_cast<const float4*>(xs);
    float4* __restrict__ out4 = reinterpret_cast<float4*>(out);

    // ILP = 8: two float4 per iteration; chains are now fully branch-free in
    // the common path so their LDS latencies overlap.
    for (int t = tid; t < T4; t += 2 * stride) {
        int t2 = t + stride;
        bool hb = t2 < T4;
        float4 a = xs4[t];
        float4 b = hb ? xs4[t2] : a;

        float v[8] = {a.x, a.y, a.z, a.w, b.x, b.y, b.z, b.w};
        float r[8];
        #pragma unroll
        for (int k = 0; k < 8; k++)
            r[k] = interp1(v[k], s_x, s_ys, s_lut, inv_w, c0);

        out4[t] = make_float4(r[0], r[1], r[2], r[3]);
        if (hb) out4[t2] = make_float4(r[4], r[5], r[6], r[7]);
    }
    for (int t = (T4 << 2) + tid; t < total; t += stride)
        out[t] = interp1(xs[t], s_x, s_ys, s_lut, inv_w, c0);
}

extern "C" void kernel_launch(void* const* d_in, const int* in_sizes, int n_in,
                              void* d_out, int out_size) {
    const float* xs = (const float*)d_in[0];
    const float* xp = (const float*)d_in[1];
    const float* yp = (const float*)d_in[2];
    float* out = (float*)d_out;
    int total = in_sizes[0];
    int n = in_sizes[1];

    build_lut_kernel<<<(LUT_SIZE + 256) / 256, 256>>>(xp, n);

    size_t smem_bytes = (size_t)(n + 8) * 4 + (size_t)n * 8
                      + (size_t)(LUT_SIZE + 2) * sizeof(unsigned short);
    cudaFuncSetAttribute(interp_kernel,
                         cudaFuncAttributeMaxDynamicSharedMemorySize,
                         (int)smem_bytes);

    int sm_count = 148, dev = 0;
    cudaGetDevice(&dev);
    cudaDeviceGetAttribute(&sm_count, cudaDevAttrMultiProcessorCount, dev);
    if (sm_count <= 0) sm_count = 148;

    interp_kernel<<<sm_count, THREADS, smem_bytes>>>(xs, xp, yp, out, total, n);
}

// round 7
// speedup vs baseline: 1.0435x; 1.0435x over previous
#include <cuda_runtime.h>
#include <cstdint>

// LinearInterpolator on GB300 — branchless bounded binary-climb.
//  lb[j] = last knot index i with cell(x_i) <= j-1. For any sample x with
//  cell(x) = j the true interval index lies in [lb[j], lb[j+1]] (window W_j).
//  Main kernel: LDS lut -> B predicated climb probes (B = ceil(log2(Wmax+1)),
//  measured from the data at stage time, compile-time unrolled via dispatch)
//  -> LDS.64 (y, slope) -> FMA. No branches, no warp votes in the hot path.

#define LUT_SIZE 16384
#define THREADS  1024
#define XPAD     64          // +INF padding; supports climb window up to 2^6

__device__ unsigned short g_lut[LUT_SIZE + 2];

__device__ __forceinline__ int cell_of(float v, float inv_w, float c0) {
    // Identical instruction sequence in build + main kernels (monotone in v).
    return (int)fmaf(v, inv_w, c0);
}

__global__ void build_lut_kernel(const float* __restrict__ xp, int n) {
    int j = blockIdx.x * blockDim.x + threadIdx.x;
    if (j > LUT_SIZE + 1) return;
    float x_lo = __ldg(&xp[0]);
    float x_hi = __ldg(&xp[n - 1]);
    float inv_w = __fdiv_rn((float)LUT_SIZE, __fsub_rn(x_hi, x_lo));
    float c0 = __fmul_rn(-x_lo, inv_w);
    // lb = (#{i : cell(x_i) <= j-1}) - 1, clamped to [0, n-2]
    int lo = 0, hi = n;
    #pragma unroll 1
    while (lo < hi) {
        int mid = (lo + hi) >> 1;
        if (cell_of(__ldg(&xp[mid]), inv_w, c0) <= j - 1) lo = mid + 1;
        else hi = mid;
    }
    int base = lo - 1;
    if (base < 0) base = 0;
    if (base > n - 2) base = n - 2;
    g_lut[j] = (unsigned short)base;
}

extern __shared__ unsigned char smem_raw[];

template <int B>
__device__ __forceinline__ float interp1(float x,
                                         const float* __restrict__ s_x,
                                         const float2* __restrict__ s_ys,
                                         const unsigned short* __restrict__ s_lut,
                                         float inv_w, float c0) {
    int j = cell_of(x, inv_w, c0);
    j = min(j, LUT_SIZE + 1);
    int idx = (int)s_lut[j];
    float xv = s_x[idx];                       // lower bound: xv <= x guaranteed
    #pragma unroll
    for (int b = B - 1; b >= 0; --b) {
        int m = idx + (1 << b);                // +INF pad keeps m in-bounds
        float xm = s_x[m];
        bool p = (xm <= x);                    // probes never accept past n-2
        idx = p ? m : idx;
        xv = p ? xm : xv;
    }
    float2 ys = s_ys[idx];                     // (y_i, slope_i)
    return fmaf(ys.y, __fsub_rn(x, xv), ys.x);
}

// Safety path for pathological inputs (cell with >63 knots); not data-reachable.
__device__ __noinline__ float interp_generic(float x, int Brt, int mclamp,
                                             const float* __restrict__ s_x,
                                             const float2* __restrict__ s_ys,
                                             const unsigned short* __restrict__ s_lut,
                                             float inv_w, float c0) {
    int j = cell_of(x, inv_w, c0);
    j = min(j, LUT_SIZE + 1);
    int idx = (int)s_lut[j];
    float xv = s_x[idx];
    #pragma unroll 1
    for (int b = Brt - 1; b >= 0; --b) {
        int m = min(idx + (1 << b), mclamp);
        float xm = s_x[m];
        bool p = (xm <= x);
        idx = p ? m : idx;
        xv = p ? xm : xv;
    }
    float2 ys = s_ys[idx];
    return fmaf(ys.y, __fsub_rn(x, xv), ys.x);
}

template <int B>
__device__ __forceinline__ void run_stream(const float4* __restrict__ xs4,
                                           float4* __restrict__ out4,
                                           const float* __restrict__ xs,
                                           float* __restrict__ out, int total,
                                           const float* __restrict__ s_x,
                                           const float2* __restrict__ s_ys,
                                           const unsigned short* __restrict__ s_lut,
                                           float inv_w, float c0) {
    int tid = blockIdx.x * blockDim.x + threadIdx.x;
    int stride = gridDim.x * blockDim.x;
    int T4 = total >> 2;
    for (int t = tid; t < T4; t += 2 * stride) {
        int t2 = t + stride;
        bool hb = t2 < T4;
        float4 a = xs4[t];
        float4 b = hb ? xs4[t2] : a;
        float v[8] = {a.x, a.y, a.z, a.w, b.x, b.y, b.z, b.w};
        float r[8];
        #pragma unroll
        for (int k = 0; k < 8; k++)
            r[k] = interp1<B>(v[k], s_x, s_ys, s_lut, inv_w, c0);
        out4[t] = make_float4(r[0], r[1], r[2], r[3]);
        if (hb) out4[t2] = make_float4(r[4], r[5], r[6], r[7]);
    }
    for (int t = (T4 << 2) + tid; t < total; t += stride)
        out[t] = interp1<B>(xs[t], s_x, s_ys, s_lut, inv_w, c0);
}

__global__ __launch_bounds__(THREADS, 1)
void interp_kernel(const float* __restrict__ xs, const float* __restrict__ xp,
                   const float* __restrict__ yp, float* __restrict__ out,
                   int total, int n) {
    float* s_x = reinterpret_cast<float*>(smem_raw);                  // n+XPAD f32
    float2* s_ys = reinterpret_cast<float2*>(smem_raw + (size_t)(n + XPAD) * 4);
    unsigned short* s_lut = reinterpret_cast<unsigned short*>(
        smem_raw + (size_t)(n + XPAD) * 4 + (size_t)n * 8);
    unsigned int* s_scr = reinterpret_cast<unsigned int*>(
        smem_raw + (size_t)(n + XPAD) * 4 + (size_t)n * 8 + (size_t)(LUT_SIZE + 4) * 2);

    // Stage knots (precomputed slope) into SMEM.
    for (int i = threadIdx.x; i < n; i += blockDim.x) {
        float xi = __ldg(&xp[i]);
        float yi = __ldg(&yp[i]);
        s_x[i] = xi;
        float sl = 0.0f;
        if (i < n - 1) sl = __fdiv_rn(__ldg(&yp[i + 1]) - yi, __ldg(&xp[i + 1]) - xi);
        s_ys[i] = make_float2(yi, sl);
    }
    if (threadIdx.x < XPAD)
        s_x[n + threadIdx.x] = __int_as_float(0x7F800000);  // +INF pad
    // Stage LUT; byproduct: max climb window W = max(lut[j+1]-lut[j]).
    unsigned int wmax = 0;
    for (int i = threadIdx.x; i < LUT_SIZE + 2; i += blockDim.x) {
        unsigned short lv = g_lut[i];
        s_lut[i] = lv;
        if (i <= LUT_SIZE) {
            unsigned int d = (unsigned int)(g_lut[i + 1] - lv);
            wmax = max(wmax, d);
        }
    }
    wmax = __reduce_max_sync(0xFFFFFFFFu, wmax);
    if ((threadIdx.x & 31) == 0) s_scr[threadIdx.x >> 5] = wmax;
    __syncthreads();

    unsigned int W = 0;
    #pragma unroll
    for (int w = 0; w < THREADS / 32; w++) W = max(W, s_scr[w]);
    int B = (W == 0) ? 0 : (32 - __clz(W));    // smallest B with 2^B > W

    float x_lo = s_x[0];
    float x_hi = s_x[n - 1];
    float inv_w = __fdiv_rn((float)LUT_SIZE, __fsub_rn(x_hi, x_lo));
    float c0 = __fmul_rn(-x_lo, inv_w);

    const float4* xs4 = reinterpret_cast<const float4*>(xs);
    float4* out4 = reinterpret_cast<float4*>(out);

    if (B <= 2)      run_stream<2>(xs4, out4, xs, out, total, s_x, s_ys, s_lut, inv_w, c0);
    else if (B == 3) run_stream<3>(xs4, out4, xs, out, total, s_x, s_ys, s_lut, inv_w, c0);
    else if (B == 4) run_stream<4>(xs4, out4, xs, out, total, s_x, s_ys, s_lut, inv_w, c0);
    else if (B == 5) run_stream<5>(xs4, out4, xs, out, total, s_x, s_ys, s_lut, inv_w, c0);
    else if (B == 6) run_stream<6>(xs4, out4, xs, out, total, s_x, s_ys, s_lut, inv_w, c0);
    else {
        int tid = blockIdx.x * blockDim.x + threadIdx.x;
        int stride = gridDim.x * blockDim.x;
        int mclamp = n + XPAD - 2;
        for (int t = tid; t < total; t += stride)
            out[t] = interp_generic(xs[t], B, mclamp, s_x, s_ys, s_lut, inv_w, c0);
    }
}

extern "C" void kernel_launch(void* const* d_in, const int* in_sizes, int n_in,
                              void* d_out, int out_size) {
    const float* xs = (const float*)d_in[0];
    const float* xp = (const float*)d_in[1];
    const float* yp = (const float*)d_in[2];
    float* out = (float*)d_out;
    int total = in_sizes[0];
    int n = in_sizes[1];

    build_lut_kernel<<<(LUT_SIZE + 2 + 255) / 256, 256>>>(xp, n);

    size_t smem_bytes = (size_t)(n + XPAD) * 4 + (size_t)n * 8
                      + (size_t)(LUT_SIZE + 4) * 2 + (THREADS / 32) * 4;
    cudaFuncSetAttribute(interp_kernel,
                         cudaFuncAttributeMaxDynamicSharedMemorySize,
                         (int)smem_bytes);

    int sm_count = 148, dev = 0;
    cudaGetDevice(&dev);
    cudaDeviceGetAttribute(&sm_count, cudaDevAttrMultiProcessorCount, dev);
    if (sm_count <= 0) sm_count = 148;

    interp_kernel<<<sm_count, THREADS, smem_bytes>>>(xs, xp, yp, out, total, n);
}